// round 8
// baseline (speedup 1.0000x reference)
#include <cuda_runtime.h>
#include <limits.h>

// Problem constants (fixed by the reference: B=16, S=2048, D=768, fp32)
#define B_DIM   16
#define S_DIM   2048
#define D_DIM   768
#define NSLOT   (B_DIM * S_DIM)
#define GSIZE   64               // threads per group (2 warps)
#define GPC     4                // groups per 256-thread CTA
#define CPL     3                // float4 columns per thread (192 / 64)
#define NCTA    (148 * 5)        // persistent grid: 5 CTAs per SM
#define NGROUP  (NCTA * GPC)     // concurrent groups

// Persistent fused kernel. Each 64-thread group walks input positions
// p = gid, gid+NGROUP, ... For each position:
//   - warp-parallel run detection from a 32-wide seg window (lane loads
//     seg[p-1+lane]); shfl gives prev/s, ballot gives run end.
//   - non-start positions are skipped (their rows belong to the run-start
//     group); run-start groups stream rows [p,end) and write the mean,
//     plus zero-fill empty output slots in the id-gap below the run.
// The NEXT position's seg window is loaded before the current position's
// streaming loop, hiding the dependent-prologue latency. Persistent warps
// never retire early, so occupancy stays flat.
__global__ __launch_bounds__(GSIZE * GPC, 5) void seg_mean_persist_kernel(
    const float* __restrict__ x,    // [B, S, D]
    const int*   __restrict__ seg,  // [B, S] sorted non-decreasing per row
    float*       __restrict__ out)  // [B, S, D]
{
    const int g    = threadIdx.x >> 6;          // group in CTA, 0..3
    const int h    = threadIdx.x & (GSIZE - 1); // lane in group, 0..63
    const int lane = h & 31;                    // lane in warp
    const int gid  = blockIdx.x * GPC + g;      // global group id

    // Window load for slot p: v = seg[b, p-1+lane] with sentinels.
    auto load_win = [&](int slot) -> int {
        const int b   = slot >> 11;
        const int p   = slot & (S_DIM - 1);
        const int idx = p - 1 + lane;
        if (idx < 0)           return -1;       // row start sentinel
        if (idx >= S_DIM)      return INT_MAX;  // row end sentinel
        return __ldg(seg + b * S_DIM + idx);
    };

    int slot = gid;
    if (slot >= NSLOT) return;
    int v = load_win(slot);

    while (true) {
        const int slot_n = slot + NGROUP;
        int v_n = 0;
        if (slot_n < NSLOT) v_n = load_win(slot_n);   // prefetch next window

        const int b    = slot >> 11;
        const int p    = slot & (S_DIM - 1);
        const int base = b * S_DIM;

        const int prev = __shfl_sync(0xffffffffu, v, 0);  // seg[p-1] (or -1)
        const int s    = __shfl_sync(0xffffffffu, v, 1);  // seg[p]

        // Trailing empty slots: handled by the last-position group.
        if (p == S_DIM - 1 && s + 1 < S_DIM) {
            const float4 z = make_float4(0.f, 0.f, 0.f, 0.f);
            for (int w = s + 1; w < S_DIM; w++) {
                float4* o = reinterpret_cast<float4*>(
                                out + (size_t)(base + w) * D_DIM) + h;
                #pragma unroll
                for (int c = 0; c < CPL; c++) __stcs(o + c * GSIZE, z);
            }
        }

        if (s != prev) {   // run start
            // Empty slots in the id-gap below this run.
            if (prev + 1 < s) {
                const float4 z = make_float4(0.f, 0.f, 0.f, 0.f);
                for (int w = prev + 1; w < s; w++) {
                    float4* o = reinterpret_cast<float4*>(
                                    out + (size_t)(base + w) * D_DIM) + h;
                    #pragma unroll
                    for (int c = 0; c < CPL; c++) __stcs(o + c * GSIZE, z);
                }
            }

            // Run end from ballot: first lane >= 2 whose id differs from s.
            const unsigned mism = __ballot_sync(0xffffffffu, v != s) & 0xFFFFFFFCu;
            int end;
            if (mism) {
                end = p - 1 + (__ffs(mism) - 1);
            } else {
                end = p + 31;                      // rare long run: serial scan
                const int* srow = seg + base;
                while (end < S_DIM && __ldg(srow + end) == s) end++;
            }
            const int cnt = end - p;

            // Stream rows [p, end): each thread owns 3 float4 columns.
            const float4* __restrict__ q = reinterpret_cast<const float4*>(
                x + (size_t)(base + p) * D_DIM) + h;

            float4 acc[CPL];
            #pragma unroll
            for (int c = 0; c < CPL; c++) acc[c] = __ldcs(q + c * GSIZE);

            for (int i = 1; i < cnt; i++) {
                q += D_DIM / 4;
                float4 t[CPL];
                #pragma unroll
                for (int c = 0; c < CPL; c++) t[c] = __ldcs(q + c * GSIZE);
                #pragma unroll
                for (int c = 0; c < CPL; c++) {
                    acc[c].x += t[c].x; acc[c].y += t[c].y;
                    acc[c].z += t[c].z; acc[c].w += t[c].w;
                }
            }

            const float inv = 1.0f / (float)cnt;
            float4* __restrict__ o = reinterpret_cast<float4*>(
                                         out + (size_t)(base + s) * D_DIM) + h;
            #pragma unroll
            for (int c = 0; c < CPL; c++) {
                acc[c].x *= inv; acc[c].y *= inv;
                acc[c].z *= inv; acc[c].w *= inv;
                __stcs(o + c * GSIZE, acc[c]);
            }
        }

        if (slot_n >= NSLOT) break;
        slot = slot_n;
        v    = v_n;
    }
}

extern "C" void kernel_launch(void* const* d_in, const int* in_sizes, int n_in,
                              void* d_out, int out_size)
{
    const float* x   = (const float*)d_in[0];  // robert_embed [16,2048,768] f32
    const int*   seg = (const int*)  d_in[1];  // seg_ids      [16,2048]     i32
    float*       out = (float*)d_out;          // [16,2048,768] f32

    seg_mean_persist_kernel<<<NCTA, GSIZE * GPC>>>(x, seg, out);
}